// round 14
// baseline (speedup 1.0000x reference)
#include <cuda_runtime.h>
#include <math.h>
#include <stdint.h>

#define D      2048
#define RNK    32
#define NST    16
#define LAYER  11
#define GRID   128
#define NTHR   1024
#define NWARP  32

typedef unsigned long long ull;

// Scratch (device globals; persist across graph replays)
__device__ float g_z1[3][D];
__device__ float g_u[2][3][D];               // [0]=f (fconv), [1]=bw (bconv)
__device__ float g_dbcA[2][3][64];            // atomic accumulator (zeroed each launch)
__device__ unsigned long long g_bar;          // monotonic grid-barrier counter

// packed f32x2 fma: d.{lo,hi} += a.{lo,hi} * b.{lo,hi}
#define FMA2(d, a, b) \
    asm("fma.rn.f32x2 %0, %1, %2, %0;" : "+l"(d) : "l"(a), "l"(b))

__device__ __forceinline__ float f2sum(ull v) {
    return __uint_as_float((unsigned)(v & 0xffffffffu))
         + __uint_as_float((unsigned)(v >> 32));
}

__device__ __forceinline__ float warp_sum(float v) {     // result in lane 0
    v += __shfl_down_sync(0xffffffffu, v, 16);
    v += __shfl_down_sync(0xffffffffu, v, 8);
    v += __shfl_down_sync(0xffffffffu, v, 4);
    v += __shfl_down_sync(0xffffffffu, v, 2);
    v += __shfl_down_sync(0xffffffffu, v, 1);
    return v;
}
__device__ __forceinline__ float warp_sum_all(float v) {  // result in ALL lanes
    v += __shfl_xor_sync(0xffffffffu, v, 16);
    v += __shfl_xor_sync(0xffffffffu, v, 8);
    v += __shfl_xor_sync(0xffffffffu, v, 4);
    v += __shfl_xor_sync(0xffffffffu, v, 2);
    v += __shfl_xor_sync(0xffffffffu, v, 1);
    return v;
}

// Grid barrier: monotonic counter, round-up target. Replay-safe (never resets).
__device__ __forceinline__ void grid_bar() {
    __syncthreads();
    if (threadIdx.x == 0) {
        __threadfence();
        unsigned long long my = atomicAdd(&g_bar, 1ull) + 1ull;
        unsigned long long target = ((my + (GRID - 1ull)) / GRID) * GRID;
        volatile unsigned long long* p = (volatile unsigned long long*)&g_bar;
        while (*p < target) { }
        __threadfence();
    }
    __syncthreads();
}

__device__ __forceinline__ float softplus_f(float v) {
    return fmaxf(v, 0.f) + log1pf(expf(-fabsf(v)));
}

// ---------------------------------------------------------------------------
// One persistent kernel: A (ln+proj) -> bar -> B (conv + fused dbc partials
// via atomics) -> bar -> D (epilogue). Only TWO grid barriers.
// ---------------------------------------------------------------------------
__global__ void __launch_bounds__(NTHR, 1) k_all(
        const float* __restrict__ x,
        const float* __restrict__ gam,
        const float* __restrict__ bet,
        const float* __restrict__ Wp,  const float* __restrict__ bp,
        const float* __restrict__ Wf,  const float* __restrict__ bf,
        const float* __restrict__ Wb,  const float* __restrict__ bb_,
        const float* __restrict__ Wdbc,
        const float* __restrict__ dtp_w,
        const float* __restrict__ dtp_b,
        const float* __restrict__ Dp,
        float* __restrict__ out) {
    __shared__ __align__(16) float s_in[3][D];   // 24 KB (xn, then z1)
    __shared__ float red[NWARP][6];
    __shared__ float s_part[NWARP][3];           // phase B: biased u rows
    __shared__ float mu_s[3], inv_s[3];
    __shared__ float s_dbc[2][3][64];
    __shared__ float s_bc[2][3];

    const int tid = threadIdx.x;
    const int w   = tid >> 5;
    const int l   = tid & 31;
    const int blk = blockIdx.x;

    const ulonglong2* X0 = (const ulonglong2*)s_in[0];
    const ulonglong2* X1 = (const ulonglong2*)s_in[1];
    const ulonglong2* X2 = (const ulonglong2*)s_in[2];

    // --- entry prefetch: first 2 weight chunks of phase A (overlaps LN) ----
    const int rw   = w >> 1;
    const int half = w & 1;
    const int rowA = blk * 16 + rw;
    const ulonglong2* wpA = (const ulonglong2*)(Wp + (size_t)rowA * D) + half * 256;
    ulonglong2 preA0 = wpA[l];
    ulonglong2 preA1 = wpA[32 + l];

    // zero the dbc accumulator for this launch (ordered before any phase-B
    // atomics by grid barrier 1)
    if (blk == 0 && tid < 2 * 3 * 64)
        (&g_dbcA[0][0][0])[tid] = 0.f;

    // ===================== Phase A: layernorm + proj ========================
    {
        float sm[3] = {0.f, 0.f, 0.f}, sq[3] = {0.f, 0.f, 0.f};
        #pragma unroll
        for (int rep = 0; rep < 2; rep++) {
            const int i = rep * NTHR + tid;
            #pragma unroll
            for (int b = 0; b < 3; b++) {
                float v = x[b * D + i];
                s_in[b][i] = v;
                sm[b] += v;
                sq[b] += v * v;
            }
        }
        #pragma unroll
        for (int b = 0; b < 3; b++) { sm[b] = warp_sum(sm[b]); sq[b] = warp_sum(sq[b]); }
        if (l == 0) {
            #pragma unroll
            for (int b = 0; b < 3; b++) { red[w][b] = sm[b]; red[w][3 + b] = sq[b]; }
        }
        __syncthreads();
        if (tid < 3) {
            float S = 0.f, Q = 0.f;
            #pragma unroll
            for (int i = 0; i < NWARP; i++) { S += red[i][tid]; Q += red[i][3 + tid]; }
            float mu = S * (1.f / D);
            float var = Q * (1.f / D) - mu * mu;
            mu_s[tid] = mu;
            inv_s[tid] = rsqrtf(var + 1e-5f);
        }
        __syncthreads();
        const float m0 = mu_s[0], m1 = mu_s[1], m2 = mu_s[2];
        const float i0 = inv_s[0], i1 = inv_s[1], i2 = inv_s[2];
        #pragma unroll
        for (int rep = 0; rep < 2; rep++) {
            const int i = rep * NTHR + tid;
            const float g = gam[i], be = bet[i];
            s_in[0][i] = (s_in[0][i] - m0) * i0 * g + be;
            s_in[1][i] = (s_in[1][i] - m1) * i1 * g + be;
            s_in[2][i] = (s_in[2][i] - m2) * i2 * g + be;
        }
        __syncthreads();

        // half-row per warp with packed f32x2 accumulation
        ull a0a = 0, a0b = 0, a1a = 0, a1b = 0, a2a = 0, a2b = 0;
        #pragma unroll
        for (int it = 0; it < 8; it++) {
            const int idx = half * 256 + it * 32 + l;
            ulonglong2 wv = (it == 0) ? preA0 : (it == 1) ? preA1 : wpA[it * 32 + l];
            ulonglong2 v0 = X0[idx], v1 = X1[idx], v2 = X2[idx];
            FMA2(a0a, wv.x, v0.x); FMA2(a0b, wv.y, v0.y);
            FMA2(a1a, wv.x, v1.x); FMA2(a1b, wv.y, v1.y);
            FMA2(a2a, wv.x, v2.x); FMA2(a2b, wv.y, v2.y);
        }
        float r0 = warp_sum(f2sum(a0a) + f2sum(a0b));
        float r1 = warp_sum(f2sum(a1a) + f2sum(a1b));
        float r2 = warp_sum(f2sum(a2a) + f2sum(a2b));
        if (l == 0) { s_part[w][0] = r0; s_part[w][1] = r1; s_part[w][2] = r2; }
        __syncthreads();
        if (tid < 48) {   // 16 rows x 3 batches
            const int rr = tid / 3, b = tid % 3;
            const int row_g = blk * 16 + rr;
            g_z1[b][row_g] = s_part[2 * rr][b] + s_part[2 * rr + 1][b] + bp[row_g];
        }
    }

    // --- prefetch phase-B weights (constants) before barrier 1 -------------
    const int whichB  = (blk >= 64) ? 1 : 0;
    const int rowbase = (blk & 63) * 32;
    const int rowB    = rowbase + w;
    const ulonglong2* wpB =
        (const ulonglong2*)((whichB ? Wb : Wf) + (size_t)rowB * D);
    ulonglong2 preB0 = wpB[l];
    ulonglong2 preB1 = wpB[32 + l];

    grid_bar();

    // ========== Phase B: f/b conv matvecs + fused dbc partials =============
    {
        #pragma unroll
        for (int rep = 0; rep < 6; rep++)
            (&s_in[0][0])[rep * NTHR + tid] = (&g_z1[0][0])[rep * NTHR + tid];
        __syncthreads();

        ull a0a = 0, a0b = 0, a1a = 0, a1b = 0, a2a = 0, a2b = 0;
        #pragma unroll
        for (int it = 0; it < 16; it++) {
            const int idx = it * 32 + l;
            ulonglong2 wv = (it == 0) ? preB0 : (it == 1) ? preB1 : wpB[idx];
            ulonglong2 v0 = X0[idx], v1 = X1[idx], v2 = X2[idx];
            FMA2(a0a, wv.x, v0.x); FMA2(a0b, wv.y, v0.y);
            FMA2(a1a, wv.x, v1.x); FMA2(a1b, wv.y, v1.y);
            FMA2(a2a, wv.x, v2.x); FMA2(a2b, wv.y, v2.y);
        }
        float r0 = warp_sum(f2sum(a0a) + f2sum(a0b));
        float r1 = warp_sum(f2sum(a1a) + f2sum(a1b));
        float r2 = warp_sum(f2sum(a2a) + f2sum(a2b));
        if (l == 0) {
            const float bv = whichB ? bb_[rowB] : bf[rowB];
            const float u0 = r0 + bv, u1 = r1 + bv, u2 = r2 + bv;
            g_u[whichB][0][rowB] = u0;
            g_u[whichB][1][rowB] = u1;
            g_u[whichB][2][rowB] = u2;
            s_part[w][0] = u0; s_part[w][1] = u1; s_part[w][2] = u2;
        }
        __syncthreads();

        // fused dbc partials: this block owns u rows [rowbase, rowbase+32).
        // For each e: partial[b] = sum_{r<32} Wdbc[e][rowbase+r] * u[b][r].
        // Each warp handles 2 e-values; lane l covers local row l.
        const float ul0 = s_part[l][0];
        const float ul1 = s_part[l][1];
        const float ul2 = s_part[l][2];
        #pragma unroll
        for (int rep = 0; rep < 2; rep++) {
            const int e = rep * 32 + w;
            const float we = Wdbc[(size_t)e * D + rowbase + l];
            float p0 = warp_sum(we * ul0);
            float p1 = warp_sum(we * ul1);
            float p2 = warp_sum(we * ul2);
            if (l == 0) {
                atomicAdd(&g_dbcA[whichB][0][e], p0);
                atomicAdd(&g_dbcA[whichB][1][e], p1);
                atomicAdd(&g_dbcA[whichB][2][e], p2);
            }
        }
    }

    // --- prefetch phase-D constants (+ z1, ready since barrier 1) ----------
    const int dD = blk * 16 + (w & 15);
    const float wrD = dtp_w[(size_t)dD * RNK + l];
    float tbD = 0.f, dpvD = 0.f, zD = 0.f, xD = 0.f;
    if (l < 3) {
        tbD  = dtp_b[dD];
        dpvD = Dp[dD];
        zD   = g_z1[l][dD];
        xD   = x[l * D + dD];
    }

    grid_bar();

    // ===================== Phase D: delta / gate / residual =================
    {
        if (tid < 2 * 3 * 64)
            (&s_dbc[0][0][0])[tid] = (&g_dbcA[0][0][0])[tid];
        __syncthreads();
        if (tid < 6) {
            const int ww = tid / 3, b = tid % 3;
            float s = 0.f;
            #pragma unroll
            for (int n = 0; n < NST; n++)
                s += s_dbc[ww][b][RNK + n] * s_dbc[ww][b][RNK + NST + n];
            s_bc[ww][b] = s;
        }
        __syncthreads();

        // warp-per-d: warps 0..15 of each block -> 2048 d's
        if (w < 16) {
            float s_f[3], s_b[3];
            #pragma unroll
            for (int b = 0; b < 3; b++) {
                s_f[b] = warp_sum_all(wrD * s_dbc[0][b][l]);
                s_b[b] = warp_sum_all(wrD * s_dbc[1][b][l]);
            }
            if (l < 3) {
                const int b = l;
                const float uf = g_u[0][b][dD];
                const float ub = g_u[1][b][dD];
                const float df = softplus_f(s_f[b] + tbD);
                const float db = softplus_f(s_b[b] + tbD);
                const float y = uf * (df * s_bc[0][b] + dpvD)
                              + ub * (db * s_bc[1][b] + dpvD);
                const float si = zD / (1.f + expf(-zD));
                out[b * D + dD] = y * si + xD;
            }
        }
    }
}

// ---------------------------------------------------------------------------
extern "C" void kernel_launch(void* const* d_in, const int* in_sizes, int n_in,
                              void* d_out, int out_size) {
    const float* x    = (const float*)d_in[0];
    const float* ng   = (const float*)d_in[1]  + (size_t)LAYER * D;
    const float* nb   = (const float*)d_in[2]  + (size_t)LAYER * D;
    const float* pw   = (const float*)d_in[3]  + (size_t)LAYER * D * D;
    const float* pb   = (const float*)d_in[4]  + (size_t)LAYER * D;
    const float* fw   = (const float*)d_in[5]  + (size_t)LAYER * D * D;
    const float* fb   = (const float*)d_in[6]  + (size_t)LAYER * D;
    const float* bw   = (const float*)d_in[7]  + (size_t)LAYER * D * D;
    const float* bb   = (const float*)d_in[8]  + (size_t)LAYER * D;
    const float* dbcw = (const float*)d_in[9]  + (size_t)LAYER * (RNK + 2 * NST) * D;
    const float* dtpw = (const float*)d_in[10] + (size_t)LAYER * D * RNK;
    const float* dtpb = (const float*)d_in[11] + (size_t)LAYER * D;
    // d_in[12] = A_log : unused (seq len 1, h0 = 0 -> dA*h term vanishes)
    const float* Dp   = (const float*)d_in[13] + (size_t)LAYER * D;
    float* out = (float*)d_out;

    k_all<<<GRID, NTHR>>>(x, ng, nb, pw, pb, fw, fb, bw, bb,
                          dbcw, dtpw, dtpb, Dp, out);
}

// round 15
// speedup vs baseline: 1.1951x; 1.1951x over previous
#include <cuda_runtime.h>
#include <math.h>
#include <stdint.h>

#define D      2048
#define RNK    32
#define NST    16
#define LAYER  11
#define GRID   128
#define NTHR   1024
#define NWARP  32

typedef unsigned long long ull;

// Scratch (device globals; persist across graph replays)
__device__ float g_z1[3][D];
__device__ float g_u[2][3][D];               // [0]=f (fconv), [1]=bw (bconv)
__device__ float g_dbc[2][3][64];
__device__ unsigned long long g_bar;          // monotonic grid-barrier counter

// packed f32x2 fma: d.{lo,hi} += a.{lo,hi} * b.{lo,hi}
#define FMA2(d, a, b) \
    asm("fma.rn.f32x2 %0, %1, %2, %0;" : "+l"(d) : "l"(a), "l"(b))

__device__ __forceinline__ float f2sum(ull v) {
    return __uint_as_float((unsigned)(v & 0xffffffffu))
         + __uint_as_float((unsigned)(v >> 32));
}

__device__ __forceinline__ float warp_sum(float v) {     // result in lane 0
    v += __shfl_down_sync(0xffffffffu, v, 16);
    v += __shfl_down_sync(0xffffffffu, v, 8);
    v += __shfl_down_sync(0xffffffffu, v, 4);
    v += __shfl_down_sync(0xffffffffu, v, 2);
    v += __shfl_down_sync(0xffffffffu, v, 1);
    return v;
}
__device__ __forceinline__ float warp_sum_all(float v) {  // result in ALL lanes
    v += __shfl_xor_sync(0xffffffffu, v, 16);
    v += __shfl_xor_sync(0xffffffffu, v, 8);
    v += __shfl_xor_sync(0xffffffffu, v, 4);
    v += __shfl_xor_sync(0xffffffffu, v, 2);
    v += __shfl_xor_sync(0xffffffffu, v, 1);
    return v;
}

// Grid barrier: monotonic counter, round-up target. Replay-safe (never resets).
__device__ __forceinline__ void grid_bar() {
    __syncthreads();
    if (threadIdx.x == 0) {
        __threadfence();
        unsigned long long my = atomicAdd(&g_bar, 1ull) + 1ull;
        unsigned long long target = ((my + (GRID - 1ull)) / GRID) * GRID;
        volatile unsigned long long* p = (volatile unsigned long long*)&g_bar;
        while (*p < target) { }
        __threadfence();
    }
    __syncthreads();
}

__device__ __forceinline__ float softplus_f(float v) {
    return fmaxf(v, 0.f) + log1pf(expf(-fabsf(v)));
}

// ---------------------------------------------------------------------------
// One persistent kernel (R13) + phase-B reads z1 straight from global (no
// staging, no extra sync; latency overlapped with weight stream).
// ---------------------------------------------------------------------------
__global__ void __launch_bounds__(NTHR, 1) k_all(
        const float* __restrict__ x,
        const float* __restrict__ gam,
        const float* __restrict__ bet,
        const float* __restrict__ Wp,  const float* __restrict__ bp,
        const float* __restrict__ Wf,  const float* __restrict__ bf,
        const float* __restrict__ Wb,  const float* __restrict__ bb_,
        const float* __restrict__ Wdbc,
        const float* __restrict__ dtp_w,
        const float* __restrict__ dtp_b,
        const float* __restrict__ Dp,
        float* __restrict__ out) {
    __shared__ __align__(16) float s_in[3][D];   // 24 KB (xn, phase A only)
    __shared__ float red[NWARP][6];
    __shared__ float s_part[NWARP][3];
    __shared__ float mu_s[3], inv_s[3];
    __shared__ float s_dbc[2][3][64];
    __shared__ float s_bc[2][3];

    const int tid = threadIdx.x;
    const int w   = tid >> 5;
    const int l   = tid & 31;
    const int blk = blockIdx.x;

    const ulonglong2* X0 = (const ulonglong2*)s_in[0];
    const ulonglong2* X1 = (const ulonglong2*)s_in[1];
    const ulonglong2* X2 = (const ulonglong2*)s_in[2];

    // --- entry prefetch: first 2 weight chunks of phase A (overlaps LN) ----
    const int rw   = w >> 1;
    const int half = w & 1;
    const int rowA = blk * 16 + rw;
    const ulonglong2* wpA = (const ulonglong2*)(Wp + (size_t)rowA * D) + half * 256;
    ulonglong2 preA0 = wpA[l];
    ulonglong2 preA1 = wpA[32 + l];

    // ===================== Phase A: layernorm + proj ========================
    {
        float sm[3] = {0.f, 0.f, 0.f}, sq[3] = {0.f, 0.f, 0.f};
        #pragma unroll
        for (int rep = 0; rep < 2; rep++) {
            const int i = rep * NTHR + tid;
            #pragma unroll
            for (int b = 0; b < 3; b++) {
                float v = x[b * D + i];
                s_in[b][i] = v;
                sm[b] += v;
                sq[b] += v * v;
            }
        }
        #pragma unroll
        for (int b = 0; b < 3; b++) { sm[b] = warp_sum(sm[b]); sq[b] = warp_sum(sq[b]); }
        if (l == 0) {
            #pragma unroll
            for (int b = 0; b < 3; b++) { red[w][b] = sm[b]; red[w][3 + b] = sq[b]; }
        }
        __syncthreads();
        if (tid < 3) {
            float S = 0.f, Q = 0.f;
            #pragma unroll
            for (int i = 0; i < NWARP; i++) { S += red[i][tid]; Q += red[i][3 + tid]; }
            float mu = S * (1.f / D);
            float var = Q * (1.f / D) - mu * mu;
            mu_s[tid] = mu;
            inv_s[tid] = rsqrtf(var + 1e-5f);
        }
        __syncthreads();
        const float m0 = mu_s[0], m1 = mu_s[1], m2 = mu_s[2];
        const float i0 = inv_s[0], i1 = inv_s[1], i2 = inv_s[2];
        #pragma unroll
        for (int rep = 0; rep < 2; rep++) {
            const int i = rep * NTHR + tid;
            const float g = gam[i], be = bet[i];
            s_in[0][i] = (s_in[0][i] - m0) * i0 * g + be;
            s_in[1][i] = (s_in[1][i] - m1) * i1 * g + be;
            s_in[2][i] = (s_in[2][i] - m2) * i2 * g + be;
        }
        __syncthreads();

        // half-row per warp with packed f32x2 accumulation
        ull a0a = 0, a0b = 0, a1a = 0, a1b = 0, a2a = 0, a2b = 0;
        #pragma unroll
        for (int it = 0; it < 8; it++) {
            const int idx = half * 256 + it * 32 + l;
            ulonglong2 wv = (it == 0) ? preA0 : (it == 1) ? preA1 : wpA[it * 32 + l];
            ulonglong2 v0 = X0[idx], v1 = X1[idx], v2 = X2[idx];
            FMA2(a0a, wv.x, v0.x); FMA2(a0b, wv.y, v0.y);
            FMA2(a1a, wv.x, v1.x); FMA2(a1b, wv.y, v1.y);
            FMA2(a2a, wv.x, v2.x); FMA2(a2b, wv.y, v2.y);
        }
        float r0 = warp_sum(f2sum(a0a) + f2sum(a0b));
        float r1 = warp_sum(f2sum(a1a) + f2sum(a1b));
        float r2 = warp_sum(f2sum(a2a) + f2sum(a2b));
        if (l == 0) { s_part[w][0] = r0; s_part[w][1] = r1; s_part[w][2] = r2; }
        __syncthreads();
        if (tid < 48) {   // 16 rows x 3 batches
            const int rr = tid / 3, b = tid % 3;
            const int row_g = blk * 16 + rr;
            g_z1[b][row_g] = s_part[2 * rr][b] + s_part[2 * rr + 1][b] + bp[row_g];
        }
    }

    // --- prefetch phase-B weights (constants) before barrier 1 -------------
    const int whichB = (blk >= 64) ? 1 : 0;
    const int rowB   = (blk & 63) * 32 + w;
    const ulonglong2* wpB =
        (const ulonglong2*)((whichB ? Wb : Wf) + (size_t)rowB * D);
    ulonglong2 preB0 = wpB[l];
    ulonglong2 preB1 = wpB[32 + l];

    grid_bar();

    // ========= Phase B: f/b conv matvecs (z1 read directly from L2) ========
    {
        const ulonglong2* Z0 = (const ulonglong2*)&g_z1[0][0];
        const ulonglong2* Z1 = (const ulonglong2*)&g_z1[1][0];
        const ulonglong2* Z2 = (const ulonglong2*)&g_z1[2][0];

        ull a0a = 0, a0b = 0, a1a = 0, a1b = 0, a2a = 0, a2b = 0;
        #pragma unroll
        for (int it = 0; it < 16; it++) {
            const int idx = it * 32 + l;
            ulonglong2 wv = (it == 0) ? preB0 : (it == 1) ? preB1 : wpB[idx];
            ulonglong2 v0 = Z0[idx], v1 = Z1[idx], v2 = Z2[idx];
            FMA2(a0a, wv.x, v0.x); FMA2(a0b, wv.y, v0.y);
            FMA2(a1a, wv.x, v1.x); FMA2(a1b, wv.y, v1.y);
            FMA2(a2a, wv.x, v2.x); FMA2(a2b, wv.y, v2.y);
        }
        float r0 = warp_sum(f2sum(a0a) + f2sum(a0b));
        float r1 = warp_sum(f2sum(a1a) + f2sum(a1b));
        float r2 = warp_sum(f2sum(a2a) + f2sum(a2b));
        if (l == 0) {
            const float bv = whichB ? bb_[rowB] : bf[rowB];
            g_u[whichB][0][rowB] = r0 + bv;
            g_u[whichB][1][rowB] = r1 + bv;
            g_u[whichB][2][rowB] = r2 + bv;
        }
    }

    // --- prefetch phase-C weights (constants) before barrier 2 -------------
    const int eC   = blk & 63;
    const int idxC = tid & 511;
    const ulonglong2* wpC = (const ulonglong2*)(Wdbc + (size_t)eC * D);
    ulonglong2 preC = wpC[idxC];

    grid_bar();

    // ===================== Phase C: dbc = dbc_w @ u (64 rows) ===============
    if (blk < 64) {
        const ulonglong2* u8 = (const ulonglong2*)&g_u[0][0][0]; // 6 vecs x 512
        const int grp = tid >> 9;          // 0: vecs 0-2, 1: vecs 3-5
        float acc[3];
        #pragma unroll
        for (int v = 0; v < 3; v++) {
            ulonglong2 uv = u8[(grp * 3 + v) * 512 + idxC];
            ull pa = 0, pb = 0;
            FMA2(pa, preC.x, uv.x);
            FMA2(pb, preC.y, uv.y);
            acc[v] = f2sum(pa) + f2sum(pb);
        }
        #pragma unroll
        for (int v = 0; v < 3; v++) acc[v] = warp_sum(acc[v]);
        if (l == 0) {
            #pragma unroll
            for (int v = 0; v < 3; v++) red[w][v] = acc[v];
        }
        __syncthreads();
        if (tid < 6) {
            const int base = (tid / 3) * 16;   // warps 0-15 grp0, 16-31 grp1
            float s = 0.f;
            #pragma unroll
            for (int i = 0; i < 16; i++) s += red[base + i][tid % 3];
            (&g_dbc[0][0][0])[tid * 64 + eC] = s;
        }
    }

    // --- prefetch EVERYTHING phase D needs except g_dbc (ready post-bar 2) --
    const int dD = blk * 16 + (w & 15);
    const float wrD = dtp_w[(size_t)dD * RNK + l];
    float tbD = 0.f, dpvD = 0.f;
    float uf = 0.f, ub = 0.f, zD = 0.f, xD = 0.f;
    if (l < 3) {
        tbD  = dtp_b[dD];
        dpvD = Dp[dD];
        uf   = g_u[0][l][dD];
        ub   = g_u[1][l][dD];
        zD   = g_z1[l][dD];
        xD   = x[l * D + dD];
    }

    grid_bar();

    // ===================== Phase D: delta / gate / residual =================
    {
        if (tid < 2 * 3 * 64)
            (&s_dbc[0][0][0])[tid] = (&g_dbc[0][0][0])[tid];
        __syncthreads();
        if (tid < 6) {
            const int ww = tid / 3, b = tid % 3;
            float s = 0.f;
            #pragma unroll
            for (int n = 0; n < NST; n++)
                s += s_dbc[ww][b][RNK + n] * s_dbc[ww][b][RNK + NST + n];
            s_bc[ww][b] = s;
        }
        __syncthreads();

        // warp-per-d: warps 0..15 of each block -> 2048 d's
        if (w < 16) {
            float s_f[3], s_b[3];
            #pragma unroll
            for (int b = 0; b < 3; b++) {
                s_f[b] = warp_sum_all(wrD * s_dbc[0][b][l]);
                s_b[b] = warp_sum_all(wrD * s_dbc[1][b][l]);
            }
            if (l < 3) {
                const int b = l;
                const float df = softplus_f(s_f[b] + tbD);
                const float db = softplus_f(s_b[b] + tbD);
                const float y = uf * (df * s_bc[0][b] + dpvD)
                              + ub * (db * s_bc[1][b] + dpvD);
                const float si = zD / (1.f + expf(-zD));
                out[b * D + dD] = y * si + xD;
            }
        }
    }
}

// ---------------------------------------------------------------------------
extern "C" void kernel_launch(void* const* d_in, const int* in_sizes, int n_in,
                              void* d_out, int out_size) {
    const float* x    = (const float*)d_in[0];
    const float* ng   = (const float*)d_in[1]  + (size_t)LAYER * D;
    const float* nb   = (const float*)d_in[2]  + (size_t)LAYER * D;
    const float* pw   = (const float*)d_in[3]  + (size_t)LAYER * D * D;
    const float* pb   = (const float*)d_in[4]  + (size_t)LAYER * D;
    const float* fw   = (const float*)d_in[5]  + (size_t)LAYER * D * D;
    const float* fb   = (const float*)d_in[6]  + (size_t)LAYER * D;
    const float* bw   = (const float*)d_in[7]  + (size_t)LAYER * D * D;
    const float* bb   = (const float*)d_in[8]  + (size_t)LAYER * D;
    const float* dbcw = (const float*)d_in[9]  + (size_t)LAYER * (RNK + 2 * NST) * D;
    const float* dtpw = (const float*)d_in[10] + (size_t)LAYER * D * RNK;
    const float* dtpb = (const float*)d_in[11] + (size_t)LAYER * D;
    // d_in[12] = A_log : unused (seq len 1, h0 = 0 -> dA*h term vanishes)
    const float* Dp   = (const float*)d_in[13] + (size_t)LAYER * D;
    float* out = (float*)d_out;

    k_all<<<GRID, NTHR>>>(x, ng, nb, pw, pb, fw, fb, bw, bb,
                          dbcw, dtpw, dtpb, Dp, out);
}